// round 7
// baseline (speedup 1.0000x reference)
#include <cuda_runtime.h>
#include <cstdint>
#include <cstddef>

// Problem constants
#define EN    1000000
#define NN    100000
#define EORI  200000
#define DD    128
#define RR    32
#define HH    128
#define NRELC 200
#define L2E   1.4426950408889634f

#define TILE_E 64
#define NT64  15625         // EN / 64 exactly
#define GRID1 148

#define AS_STRIDE 132       // floats; conflict-free A-fragment LDS
#define BS_STRIDE 136       // floats; [n][perm(k)], conflict-free per phase
#define ABUF_U32  (TILE_E * AS_STRIDE)             // 8448

// smem offsets (uint32 units)
#define BS_OFF   0
#define AS_OFF   (128 * BS_STRIDE)                 // 17408
#define STAT_OFF (AS_OFF + 2 * ABUF_U32)           // 34304
#define SMEM_U32 (STAT_OFF + 256)                  // 34560 -> 138240 B

// ---------------- scratch globals ----------------
__device__ float g_h[(size_t)EN * HH];   // 512 MB pre-BN activations
__device__ float g_w[EN];
__device__ float g_sum[HH];
__device__ float g_sumsq[HH];
__device__ float g_ginv[HH];
__device__ float g_shift[HH];
__device__ unsigned g_nmax[NN];
__device__ float g_nsum[NN];
__device__ unsigned char g_flag[EN];
__device__ float g_prec[NRELC * HH];

// ---------------- helpers ----------------
__device__ __forceinline__ uint32_t tf32u(float x) {
    uint32_t o; asm("cvt.rna.tf32.f32 %0, %1;" : "=r"(o) : "f"(x)); return o;
}
__device__ __forceinline__ void mma_tf32(float c[4], const uint32_t a[4],
                                         const uint32_t b[2]) {
    asm volatile(
        "mma.sync.aligned.m16n8k8.row.col.f32.tf32.tf32.f32 "
        "{%0,%1,%2,%3}, {%4,%5,%6,%7}, {%8,%9}, {%0,%1,%2,%3};"
        : "+f"(c[0]), "+f"(c[1]), "+f"(c[2]), "+f"(c[3])
        : "r"(a[0]), "r"(a[1]), "r"(a[2]), "r"(a[3]), "r"(b[0]), "r"(b[1]));
}
__device__ __forceinline__ unsigned encf(float f) {
    unsigned u = __float_as_uint(f);
    return (u & 0x80000000u) ? ~u : (u | 0x80000000u);
}
__device__ __forceinline__ float decf(unsigned u) {
    return __uint_as_float((u & 0x80000000u) ? (u & 0x7fffffffu) : ~u);
}
// pack k and k+4 adjacent: one LDS.64 per B fragment
__device__ __forceinline__ int permk(int k) {
    return (k & ~7) | ((k & 3) << 1) | ((k >> 2) & 1);
}

// ---------------- small kernels ----------------
__global__ void k_init() {
    int i = blockIdx.x * blockDim.x + threadIdx.x;
    if (i < HH) { g_sum[i] = 0.f; g_sumsq[i] = 0.f; }
    if (i < NN) { g_nmax[i] = 0u; g_nsum[i] = 0.f; }
    if (i < EN) g_flag[i] = 0;
}
__global__ void k_flag(const int* __restrict__ ori) {
    int i = blockIdx.x * blockDim.x + threadIdx.x;
    if (i < EORI) g_flag[ori[i]] = 1;
}
__global__ void k_prec(const float* __restrict__ rel,
                       const float* __restrict__ W0,
                       const float* __restrict__ b0) {
    int i = blockIdx.x * blockDim.x + threadIdx.x;
    if (i >= NRELC * HH) return;
    int r = i / HH, c = i % HH;
    float s = b0[c];
#pragma unroll
    for (int k = 0; k < RR; k++)
        s = fmaf(rel[r * RR + k], W0[(DD + k) * HH + c], s);
    g_prec[i] = s;
}

// ---------------- pass1 ------------------------------------------------------
// Persistent 148 x 512 (16 warps). Tile = 64 edges x 128 ch, K = 128.
// Role-alternating specialization: per iteration, 8 warps MMA+epilogue tile t
// while the other 8 warps gather/exp tile t+1 into the other A buffer.

__device__ __forceinline__ void produce64(uint32_t* __restrict__ As,
                                          const float* __restrict__ nf,
                                          const int* __restrict__ rowv,
                                          const int* __restrict__ colv,
                                          int tile, int ptid) {
    const int le = ptid >> 2, seg = ptid & 3;     // 4 threads/edge, 32 dims each
    const int e = tile * TILE_E + le;             // always < EN (EN % 64 == 0)
    const int rn = rowv[e], cn = colv[e];
    const float4* ra = (const float4*)(nf + (size_t)rn * DD) + seg * 8;
    const float4* rb = (const float4*)(nf + (size_t)cn * DD) + seg * 8;
    uint32_t* arow = As + le * AS_STRIDE + seg * 32;
#pragma unroll
    for (int j = 0; j < 8; j++) {
        float4 a = ra[j], b = rb[j];
        uint4 s;
        s.x = tf32u(exp2f(-L2E * fabsf(a.x - b.x)));
        s.y = tf32u(exp2f(-L2E * fabsf(a.y - b.y)));
        s.z = tf32u(exp2f(-L2E * fabsf(a.z - b.z)));
        s.w = tf32u(exp2f(-L2E * fabsf(a.w - b.w)));
        *(uint4*)(arow + j * 4) = s;
    }
}

__global__ __launch_bounds__(512, 1) void k_pass1(
    const float* __restrict__ nf,
    const float* __restrict__ W0,
    const int* __restrict__ rowv,
    const int* __restrict__ colv,
    const int* __restrict__ etype) {
    extern __shared__ uint32_t sm[];
    uint32_t* Bs = sm + BS_OFF;              // [128 n][BS_STRIDE perm-k]
    uint32_t* As0 = sm + AS_OFF;             // [64 m][AS_STRIDE k] x2 buffers
    uint32_t* As1 = As0 + ABUF_U32;
    float* ssum = (float*)(sm + STAT_OFF);
    float* ssq  = ssum + 128;

    const int tid = threadIdx.x;
    const int wid = tid >> 5, lane = tid & 31;
    const int gid = lane >> 2, tg = lane & 3;
    const int grp = wid >> 3;                // 0 or 1
    const int cwid = wid & 7;                // consumer-role warp id
    const int wm = cwid >> 2, wn = cwid & 3;
    const int m0 = wm * 32, n0 = wn * 32;
    const int ptid = (cwid << 5) | lane;     // producer-role thread id 0..255

    // B = W0[:128,:] tf32 bits, [n][perm(k)]
    for (int i = tid; i < 128 * 128; i += 512) {
        int k = i >> 7, n = i & 127;
        Bs[n * BS_STRIDE + permk(k)] = tf32u(W0[i]);
    }
    if (tid < HH) { ssum[tid] = 0.f; ssq[tid] = 0.f; }

    // per-thread BN accumulators; col(nt,h) = n0 + nt*8 + tg*2 + h
    float ps[8], pq[8];
#pragma unroll
    for (int i = 0; i < 8; i++) { ps[i] = 0.f; pq[i] = 0.f; }

    // prologue: group 1 produces the first tile into As0
    if (grp == 1) produce64(As0, nf, rowv, colv, blockIdx.x, ptid);

    int it = 0;
    for (int tile = blockIdx.x; tile < NT64; tile += GRID1, it++) {
        __syncthreads();
        const int buf = it & 1;
        const bool iscons = (grp == 0) == ((it & 1) == 0);

        if (iscons) {
            uint32_t* Ab = buf ? As1 : As0;

            // prefetch etype for this warp's 4 epilogue rows
            int et4[4];
#pragma unroll
            for (int q = 0; q < 4; q++) {
                const int row = m0 + (q >> 1) * 16 + (q & 1) * 8 + gid;
                et4[q] = etype[tile * TILE_E + row];
            }

            // ---- MMA: 2 m-tiles x 4 n-tiles x 16 k-tiles ----
            float acc[2][4][4];
#pragma unroll
            for (int mt = 0; mt < 2; mt++)
#pragma unroll
                for (int nt = 0; nt < 4; nt++)
#pragma unroll
                    for (int r = 0; r < 4; r++) acc[mt][nt][r] = 0.f;

#pragma unroll
            for (int kt = 0; kt < 16; kt++) {
                const int k0 = kt * 8;
                uint32_t afr[2][4];
#pragma unroll
                for (int mt = 0; mt < 2; mt++) {
                    const uint32_t* ab = Ab + (m0 + mt * 16 + gid) * AS_STRIDE + k0 + tg;
                    afr[mt][0] = ab[0];
                    afr[mt][1] = ab[8 * AS_STRIDE];
                    afr[mt][2] = ab[4];
                    afr[mt][3] = ab[8 * AS_STRIDE + 4];
                }
                uint32_t bfr[4][2];
#pragma unroll
                for (int nt = 0; nt < 4; nt++) {
                    uint2 bb = *(const uint2*)(Bs + (n0 + nt * 8 + gid) * BS_STRIDE
                                               + k0 + tg * 2);
                    bfr[nt][0] = bb.x;
                    bfr[nt][1] = bb.y;
                }
#pragma unroll
                for (int mt = 0; mt < 2; mt++)
#pragma unroll
                    for (int nt = 0; nt < 4; nt++)
                        mma_tf32(acc[mt][nt], afr[mt], bfr[nt]);
            }

            // ---- epilogue: + prec[etype], store g_h, accumulate stats ----
#pragma unroll
            for (int mt = 0; mt < 2; mt++) {
#pragma unroll
                for (int rr = 0; rr < 2; rr++) {
                    const int row = m0 + mt * 16 + rr * 8 + gid;
                    const int e = tile * TILE_E + row;
                    const int et = et4[mt * 2 + rr];
                    const float2* prow = (const float2*)(g_prec + et * HH);
                    float2* hrow = (float2*)(g_h + (size_t)e * HH);
#pragma unroll
                    for (int nt = 0; nt < 4; nt++) {
                        const int c2i = (n0 + nt * 8 + tg * 2) >> 1;
                        float2 p = prow[c2i];
                        float v0 = acc[mt][nt][rr * 2 + 0] + p.x;
                        float v1 = acc[mt][nt][rr * 2 + 1] + p.y;
                        hrow[c2i] = make_float2(v0, v1);
                        ps[nt * 2 + 0] += v0; pq[nt * 2 + 0] = fmaf(v0, v0, pq[nt * 2 + 0]);
                        ps[nt * 2 + 1] += v1; pq[nt * 2 + 1] = fmaf(v1, v1, pq[nt * 2 + 1]);
                    }
                }
            }
        } else {
            // producer role: fill the other buffer with the next tile
            if (tile + GRID1 < NT64) {
                uint32_t* An = buf ? As0 : As1;
                produce64(An, nf, rowv, colv, tile + GRID1, ptid);
            }
        }
    }

    // ---- final BN stat reduction: regs -> smem -> global ----
    __syncthreads();
#pragma unroll
    for (int nt = 0; nt < 4; nt++) {
#pragma unroll
        for (int h = 0; h < 2; h++) {
            const int col = n0 + nt * 8 + tg * 2 + h;
            atomicAdd(&ssum[col], ps[nt * 2 + h]);
            atomicAdd(&ssq[col], pq[nt * 2 + h]);
        }
    }
    __syncthreads();
    if (tid < HH) {
        atomicAdd(&g_sum[tid], ssum[tid]);
        atomicAdd(&g_sumsq[tid], ssq[tid]);
    }
}

// ---------------- BN params ----------------
__global__ void k_stats(const float* __restrict__ gamma,
                        const float* __restrict__ beta) {
    int c = threadIdx.x;
    if (c >= HH) return;
    float mu = g_sum[c] * (1.0f / EN);
    float var = g_sumsq[c] * (1.0f / EN) - mu * mu;
    float gi = gamma[c] * rsqrtf(var + 1e-5f);
    g_ginv[c] = gi;
    g_shift[c] = beta[c] - mu * gi;
}

// ---------------- pass3: w = leaky(BN(h))@W1 + b1, blend, node max ------------
__global__ __launch_bounds__(256) void k_pass3(const int* __restrict__ colv,
                                               const float* __restrict__ W1,
                                               const float* __restrict__ b1) {
    int lane = threadIdx.x & 31;
    int warp = (blockIdx.x * blockDim.x + threadIdx.x) >> 5;
    int nwarp = (gridDim.x * blockDim.x) >> 5;
    float4 gi = *(const float4*)(g_ginv + lane * 4);
    float4 sh = *(const float4*)(g_shift + lane * 4);
    float4 w1 = *(const float4*)(W1 + lane * 4);
    float b1v = b1[0];
    for (int e = warp; e < EN; e += nwarp) {
        float4 h = *(const float4*)(g_h + (size_t)e * HH + lane * 4);
        float t, l, s;
        t = fmaf(h.x, gi.x, sh.x); l = fmaxf(t, 0.f) + 0.01f * fminf(t, 0.f); s = l * w1.x;
        t = fmaf(h.y, gi.y, sh.y); l = fmaxf(t, 0.f) + 0.01f * fminf(t, 0.f); s = fmaf(l, w1.y, s);
        t = fmaf(h.z, gi.z, sh.z); l = fmaxf(t, 0.f) + 0.01f * fminf(t, 0.f); s = fmaf(l, w1.z, s);
        t = fmaf(h.w, gi.w, sh.w); l = fmaxf(t, 0.f) + 0.01f * fminf(t, 0.f); s = fmaf(l, w1.w, s);
        s += __shfl_xor_sync(0xffffffffu, s, 16);
        s += __shfl_xor_sync(0xffffffffu, s, 8);
        s += __shfl_xor_sync(0xffffffffu, s, 4);
        s += __shfl_xor_sync(0xffffffffu, s, 2);
        s += __shfl_xor_sync(0xffffffffu, s, 1);
        if (lane == 0) {
            float wv = s + b1v;
            if (g_flag[e]) wv = 0.5f * wv + 0.5f;
            g_w[e] = wv;
            atomicMax(&g_nmax[colv[e]], encf(wv));
        }
    }
}

__global__ void k_pass4(const int* __restrict__ colv) {
    int e = blockIdx.x * blockDim.x + threadIdx.x;
    if (e >= EN) return;
    float wv = g_w[e];
    int cn = colv[e];
    float m = decf(g_nmax[cn]);
    float ev = exp2f((wv - m) * L2E);
    g_w[e] = ev;
    atomicAdd(&g_nsum[cn], ev);
}

__global__ void k_pass5(const int* __restrict__ colv, float* __restrict__ out) {
    int e = blockIdx.x * blockDim.x + threadIdx.x;
    if (e >= EN) return;
    int cn = colv[e];
    float o = g_w[e] / g_nsum[cn];
    out[e] = (o > 1e-4f) ? o : 0.f;
}

// ---------------- launch ----------------
extern "C" void kernel_launch(void* const* d_in, const int* in_sizes, int n_in,
                              void* d_out, int out_size) {
    const float* n_feat  = (const float*)d_in[0];
    const float* rel_emb = (const float*)d_in[1];
    const float* W0      = (const float*)d_in[2];
    const float* b0      = (const float*)d_in[3];
    const float* gamma   = (const float*)d_in[4];
    const float* beta    = (const float*)d_in[5];
    const float* W1      = (const float*)d_in[6];
    const float* b1      = (const float*)d_in[7];
    const int*   rowv    = (const int*)d_in[8];
    const int*   colv    = (const int*)d_in[9];
    const int*   etype   = (const int*)d_in[10];
    const int*   ori     = (const int*)d_in[11];
    float* out = (float*)d_out;

    const int smem1 = SMEM_U32 * 4;   // 138,240 B
    static bool attr_done = false;
    if (!attr_done) {
        cudaFuncSetAttribute(k_pass1, cudaFuncAttributeMaxDynamicSharedMemorySize, smem1);
        attr_done = true;
    }

    k_init<<<(EN + 255) / 256, 256>>>();
    k_flag<<<(EORI + 255) / 256, 256>>>(ori);
    k_prec<<<(NRELC * HH + 255) / 256, 256>>>(rel_emb, W0, b0);
    k_pass1<<<GRID1, 512, smem1>>>(n_feat, W0, rowv, colv, etype);
    k_stats<<<1, 128>>>(gamma, beta);
    k_pass3<<<2048, 256>>>(colv, W1, b1);
    k_pass4<<<(EN + 255) / 256, 256>>>(colv);
    k_pass5<<<(EN + 255) / 256, 256>>>(colv, out);
}

// round 8
// speedup vs baseline: 1.4619x; 1.4619x over previous
#include <cuda_runtime.h>
#include <cstdint>
#include <cstddef>

// Problem constants
#define EN    1000000
#define NN    100000
#define EORI  200000
#define DD    128
#define RR    32
#define HH    128
#define NRELC 200
#define L2E   1.4426950408889634f

#define NT    7813          // ceil(EN/128)
#define GRID1 148

#define AS_STRIDE 132       // floats; conflict-free A-fragment LDS
#define BS_STRIDE 136       // floats; [n][perm(k)] rows
#define STG_STRIDE 20       // float2 units per stage row (16 used + 4 pad)

// smem offsets (uint32 units)
#define BS_OFF   0
#define AS_OFF   (128 * BS_STRIDE)                 // 17408
#define STAT_OFF (AS_OFF + 128 * AS_STRIDE)        // 34304
#define STG_OFF  (STAT_OFF + 256)                  // 34560
#define SMEM_U32 (STG_OFF + 16 * 32 * STG_STRIDE * 2)  // +20480 -> 55040 u32 = 220160 B

// ---------------- scratch globals ----------------
__device__ float g_h[(size_t)EN * HH];   // 512 MB pre-BN activations
__device__ float g_w[EN];
__device__ float g_sum[HH];
__device__ float g_sumsq[HH];
__device__ float g_ginv[HH];
__device__ float g_shift[HH];
__device__ unsigned g_nmax[NN];
__device__ float g_nsum[NN];
__device__ unsigned char g_flag[EN];
__device__ float g_prec[NRELC * HH];

// ---------------- helpers ----------------
__device__ __forceinline__ uint32_t tf32u(float x) {
    uint32_t o; asm("cvt.rna.tf32.f32 %0, %1;" : "=r"(o) : "f"(x)); return o;
}
__device__ __forceinline__ void mma_tf32(float c[4], const uint32_t a[4],
                                         const uint32_t b[2]) {
    asm volatile(
        "mma.sync.aligned.m16n8k8.row.col.f32.tf32.tf32.f32 "
        "{%0,%1,%2,%3}, {%4,%5,%6,%7}, {%8,%9}, {%0,%1,%2,%3};"
        : "+f"(c[0]), "+f"(c[1]), "+f"(c[2]), "+f"(c[3])
        : "r"(a[0]), "r"(a[1]), "r"(a[2]), "r"(a[3]), "r"(b[0]), "r"(b[1]));
}
__device__ __forceinline__ unsigned encf(float f) {
    unsigned u = __float_as_uint(f);
    return (u & 0x80000000u) ? ~u : (u | 0x80000000u);
}
__device__ __forceinline__ float decf(unsigned u) {
    return __uint_as_float((u & 0x80000000u) ? (u & 0x7fffffffu) : ~u);
}
// pack k and k+4 adjacent: one LDS.64 per B fragment
__device__ __forceinline__ int permk(int k) {
    return (k & ~7) | ((k & 3) << 1) | ((k >> 2) & 1);
}

// ---------------- small kernels ----------------
__global__ void k_init() {
    int i = blockIdx.x * blockDim.x + threadIdx.x;
    if (i < HH) { g_sum[i] = 0.f; g_sumsq[i] = 0.f; }
    if (i < NN) { g_nmax[i] = 0u; g_nsum[i] = 0.f; }
    if (i < EN) g_flag[i] = 0;
}
__global__ void k_flag(const int* __restrict__ ori) {
    int i = blockIdx.x * blockDim.x + threadIdx.x;
    if (i < EORI) g_flag[ori[i]] = 1;
}
__global__ void k_prec(const float* __restrict__ rel,
                       const float* __restrict__ W0,
                       const float* __restrict__ b0) {
    int i = blockIdx.x * blockDim.x + threadIdx.x;
    if (i >= NRELC * HH) return;
    int r = i / HH, c = i % HH;
    float s = b0[c];
#pragma unroll
    for (int k = 0; k < RR; k++)
        s = fmaf(rel[r * RR + k], W0[(DD + k) * HH + c], s);
    g_prec[i] = s;
}

// ---------------- pass1 ------------------------------------------------------
// Persistent 148 x 512 (16 warps). Tile = 128 edges x 128 ch, K = 128.
// Warp grid 4(m) x 4(n); warp tile 32x32 via m16n8k8 tf32.
// Coalesced produce: warp owns 8 edges; per node-row one full-warp LDG.128.
__global__ __launch_bounds__(512, 1) void k_pass1(
    const float* __restrict__ nf,
    const float* __restrict__ W0,
    const int* __restrict__ rowv,
    const int* __restrict__ colv,
    const int* __restrict__ etype) {
    extern __shared__ uint32_t sm[];
    uint32_t* Bs = sm + BS_OFF;              // [128 n][BS_STRIDE perm-k]
    uint32_t* As = sm + AS_OFF;              // [128 m][AS_STRIDE k]
    float* ssum = (float*)(sm + STAT_OFF);
    float* ssq  = ssum + 128;

    const int tid = threadIdx.x;
    const int wid = tid >> 5, lane = tid & 31;
    const int gid = lane >> 2, tg = lane & 3;
    const int wm = wid >> 2, wn = wid & 3;
    const int m0 = wm * 32, n0 = wn * 32;
    float2* stg = (float2*)(sm + STG_OFF) + wid * 32 * STG_STRIDE;

    // B = W0[:128,:] tf32 bits, [n][perm(k)]
    for (int i = tid; i < 128 * 128; i += 512) {
        int k = i >> 7, n = i & 127;
        Bs[n * BS_STRIDE + permk(k)] = tf32u(W0[i]);
    }
    if (tid < HH) { ssum[tid] = 0.f; ssq[tid] = 0.f; }

    // per-thread BN accumulators; col(nt,h) = n0 + nt*8 + tg*2 + h
    float ps[8], pq[8];
#pragma unroll
    for (int i = 0; i < 8; i++) { ps[i] = 0.f; pq[i] = 0.f; }

    for (int tile = blockIdx.x; tile < NT; tile += GRID1) {
        // ---- produce sim tile (tf32) into As: warp owns edges wid*8..+7 ----
        {
            const int e0 = tile * 128 + wid * 8;
            int idx = 0;
            {
                int q = e0 + (lane & 7);
                q = (q < EN) ? q : (EN - 1);
                if (lane < 16) idx = (lane < 8) ? rowv[q] : colv[q];
            }
#pragma unroll 2
            for (int i = 0; i < 8; i++) {
                const int rn = __shfl_sync(0xffffffffu, idx, i);
                const int cn = __shfl_sync(0xffffffffu, idx, i + 8);
                float4 a = *(const float4*)(nf + (size_t)rn * DD + lane * 4);
                float4 b = *(const float4*)(nf + (size_t)cn * DD + lane * 4);
                uint4 s;
                s.x = tf32u(exp2f(-L2E * fabsf(a.x - b.x)));
                s.y = tf32u(exp2f(-L2E * fabsf(a.y - b.y)));
                s.z = tf32u(exp2f(-L2E * fabsf(a.z - b.z)));
                s.w = tf32u(exp2f(-L2E * fabsf(a.w - b.w)));
                *(uint4*)(As + (wid * 8 + i) * AS_STRIDE + lane * 4) = s;
            }
        }
        __syncthreads();

        // prefetch etype for this warp's 4 epilogue rows (hides under MMA)
        int et4[4];
#pragma unroll
        for (int q = 0; q < 4; q++) {
            const int row = m0 + (q >> 1) * 16 + (q & 1) * 8 + gid;
            const int e = tile * 128 + row;
            et4[q] = (e < EN) ? etype[e] : 0;
        }

        // ---- MMA: 2 m-tiles x 4 n-tiles x 16 k-tiles ----
        float acc[2][4][4];
#pragma unroll
        for (int mt = 0; mt < 2; mt++)
#pragma unroll
            for (int nt = 0; nt < 4; nt++)
#pragma unroll
                for (int r = 0; r < 4; r++) acc[mt][nt][r] = 0.f;

#pragma unroll
        for (int kt = 0; kt < 16; kt++) {
            const int k0 = kt * 8;
            uint32_t afr[2][4];
#pragma unroll
            for (int mt = 0; mt < 2; mt++) {
                const uint32_t* ab = As + (m0 + mt * 16 + gid) * AS_STRIDE + k0 + tg;
                afr[mt][0] = ab[0];
                afr[mt][1] = ab[8 * AS_STRIDE];
                afr[mt][2] = ab[4];
                afr[mt][3] = ab[8 * AS_STRIDE + 4];
            }
            uint32_t bfr[4][2];
#pragma unroll
            for (int nt = 0; nt < 4; nt++) {
                uint2 bb = *(const uint2*)(Bs + (n0 + nt * 8 + gid) * BS_STRIDE
                                           + k0 + tg * 2);
                bfr[nt][0] = bb.x;
                bfr[nt][1] = bb.y;
            }
#pragma unroll
            for (int mt = 0; mt < 2; mt++)
#pragma unroll
                for (int nt = 0; nt < 4; nt++)
                    mma_tf32(acc[mt][nt], afr[mt], bfr[nt]);
        }
        __syncthreads();   // As free for next produce

        // ---- epilogue: + prec, stats, stage in smem, coalesced STG.128 ----
#pragma unroll
        for (int mt = 0; mt < 2; mt++) {
#pragma unroll
            for (int rr = 0; rr < 2; rr++) {
                const int lrow = mt * 16 + rr * 8 + gid;   // 0..31 within warp tile
                const int e = tile * 128 + m0 + lrow;
                if (e < EN) {
                    const int et = et4[mt * 2 + rr];
                    const float2* prow = (const float2*)(g_prec + et * HH);
#pragma unroll
                    for (int nt = 0; nt < 4; nt++) {
                        const int c2g = (n0 + nt * 8 + tg * 2) >> 1;
                        float2 p = prow[c2g];
                        float v0 = acc[mt][nt][rr * 2 + 0] + p.x;
                        float v1 = acc[mt][nt][rr * 2 + 1] + p.y;
                        stg[lrow * STG_STRIDE + nt * 4 + tg] = make_float2(v0, v1);
                        ps[nt * 2 + 0] += v0; pq[nt * 2 + 0] = fmaf(v0, v0, pq[nt * 2 + 0]);
                        ps[nt * 2 + 1] += v1; pq[nt * 2 + 1] = fmaf(v1, v1, pq[nt * 2 + 1]);
                    }
                }
            }
        }
        __syncwarp();
#pragma unroll
        for (int s = 0; s < 8; s++) {
            const int lrow = s * 4 + (lane >> 3);
            const int e = tile * 128 + m0 + lrow;
            if (e < EN) {
                float4 v = *(const float4*)(stg + lrow * STG_STRIDE + (lane & 7) * 2);
                *(float4*)(g_h + (size_t)e * HH + n0 + (lane & 7) * 4) = v;
            }
        }
        __syncwarp();
    }

    // ---- final BN stat reduction: regs -> smem -> global ----
    __syncthreads();
#pragma unroll
    for (int nt = 0; nt < 4; nt++) {
#pragma unroll
        for (int h = 0; h < 2; h++) {
            const int col = n0 + nt * 8 + tg * 2 + h;
            atomicAdd(&ssum[col], ps[nt * 2 + h]);
            atomicAdd(&ssq[col], pq[nt * 2 + h]);
        }
    }
    __syncthreads();
    if (tid < HH) {
        atomicAdd(&g_sum[tid], ssum[tid]);
        atomicAdd(&g_sumsq[tid], ssq[tid]);
    }
}

// ---------------- BN params ----------------
__global__ void k_stats(const float* __restrict__ gamma,
                        const float* __restrict__ beta) {
    int c = threadIdx.x;
    if (c >= HH) return;
    float mu = g_sum[c] * (1.0f / EN);
    float var = g_sumsq[c] * (1.0f / EN) - mu * mu;
    float gi = gamma[c] * rsqrtf(var + 1e-5f);
    g_ginv[c] = gi;
    g_shift[c] = beta[c] - mu * gi;
}

// ---------------- pass3: w = leaky(BN(h))@W1 + b1, blend, node max ------------
__global__ __launch_bounds__(256) void k_pass3(const int* __restrict__ colv,
                                               const float* __restrict__ W1,
                                               const float* __restrict__ b1) {
    int lane = threadIdx.x & 31;
    int warp = (blockIdx.x * blockDim.x + threadIdx.x) >> 5;
    int nwarp = (gridDim.x * blockDim.x) >> 5;
    float4 gi = *(const float4*)(g_ginv + lane * 4);
    float4 sh = *(const float4*)(g_shift + lane * 4);
    float4 w1 = *(const float4*)(W1 + lane * 4);
    float b1v = b1[0];
    for (int e = warp; e < EN; e += nwarp) {
        float4 h = *(const float4*)(g_h + (size_t)e * HH + lane * 4);
        float t, l, s;
        t = fmaf(h.x, gi.x, sh.x); l = fmaxf(t, 0.f) + 0.01f * fminf(t, 0.f); s = l * w1.x;
        t = fmaf(h.y, gi.y, sh.y); l = fmaxf(t, 0.f) + 0.01f * fminf(t, 0.f); s = fmaf(l, w1.y, s);
        t = fmaf(h.z, gi.z, sh.z); l = fmaxf(t, 0.f) + 0.01f * fminf(t, 0.f); s = fmaf(l, w1.z, s);
        t = fmaf(h.w, gi.w, sh.w); l = fmaxf(t, 0.f) + 0.01f * fminf(t, 0.f); s = fmaf(l, w1.w, s);
        s += __shfl_xor_sync(0xffffffffu, s, 16);
        s += __shfl_xor_sync(0xffffffffu, s, 8);
        s += __shfl_xor_sync(0xffffffffu, s, 4);
        s += __shfl_xor_sync(0xffffffffu, s, 2);
        s += __shfl_xor_sync(0xffffffffu, s, 1);
        if (lane == 0) {
            float wv = s + b1v;
            if (g_flag[e]) wv = 0.5f * wv + 0.5f;
            g_w[e] = wv;
            atomicMax(&g_nmax[colv[e]], encf(wv));
        }
    }
}

__global__ void k_pass4(const int* __restrict__ colv) {
    int e = blockIdx.x * blockDim.x + threadIdx.x;
    if (e >= EN) return;
    float wv = g_w[e];
    int cn = colv[e];
    float m = decf(g_nmax[cn]);
    float ev = exp2f((wv - m) * L2E);
    g_w[e] = ev;
    atomicAdd(&g_nsum[cn], ev);
}

__global__ void k_pass5(const int* __restrict__ colv, float* __restrict__ out) {
    int e = blockIdx.x * blockDim.x + threadIdx.x;
    if (e >= EN) return;
    int cn = colv[e];
    float o = g_w[e] / g_nsum[cn];
    out[e] = (o > 1e-4f) ? o : 0.f;
}

// ---------------- launch ----------------
extern "C" void kernel_launch(void* const* d_in, const int* in_sizes, int n_in,
                              void* d_out, int out_size) {
    const float* n_feat  = (const float*)d_in[0];
    const float* rel_emb = (const float*)d_in[1];
    const float* W0      = (const float*)d_in[2];
    const float* b0      = (const float*)d_in[3];
    const float* gamma   = (const float*)d_in[4];
    const float* beta    = (const float*)d_in[5];
    const float* W1      = (const float*)d_in[6];
    const float* b1      = (const float*)d_in[7];
    const int*   rowv    = (const int*)d_in[8];
    const int*   colv    = (const int*)d_in[9];
    const int*   etype   = (const int*)d_in[10];
    const int*   ori     = (const int*)d_in[11];
    float* out = (float*)d_out;

    const int smem1 = SMEM_U32 * 4;   // 220,160 B
    static bool attr_done = false;
    if (!attr_done) {
        cudaFuncSetAttribute(k_pass1, cudaFuncAttributeMaxDynamicSharedMemorySize, smem1);
        attr_done = true;
    }

    k_init<<<(EN + 255) / 256, 256>>>();
    k_flag<<<(EORI + 255) / 256, 256>>>(ori);
    k_prec<<<(NRELC * HH + 255) / 256, 256>>>(rel_emb, W0, b0);
    k_pass1<<<GRID1, 512, smem1>>>(n_feat, W0, rowv, colv, etype);
    k_stats<<<1, 128>>>(gamma, beta);
    k_pass3<<<2048, 256>>>(colv, W1, b1);
    k_pass4<<<(EN + 255) / 256, 256>>>(colv);
    k_pass5<<<(EN + 255) / 256, 256>>>(colv, out);
}

// round 10
// speedup vs baseline: 1.5704x; 1.0742x over previous
#include <cuda_runtime.h>
#include <cstdint>
#include <cstddef>

// Problem constants
#define EN    1000000
#define NN    100000
#define EORI  200000
#define DD    128
#define RR    32
#define HH    128
#define NRELC 200
#define L2E   1.4426950408889634f

#define NT    7813          // ceil(EN/128)
#define GRID1 148

#define AS_STRIDE 132       // floats; conflict-free A-fragment LDS
#define BS_STRIDE 136       // floats; [n][perm(k)] rows
#define STG_STRIDE 20       // float2 units per stage row (16 used + 4 pad)

// smem offsets (uint32 units)
#define BS_OFF   0
#define AS_OFF   (128 * BS_STRIDE)                 // 17408
#define STAT_OFF (AS_OFF + 128 * AS_STRIDE)        // 34304
#define STG_OFF  (STAT_OFF + 256)                  // 34560
#define SMEM_U32 (STG_OFF + 16 * 32 * STG_STRIDE * 2)  // 55040 u32 = 220160 B

// ---------------- scratch globals ----------------
__device__ float g_h[(size_t)EN * HH];   // 512 MB pre-BN activations
__device__ float g_w[EN];                // exp(w) per edge
__device__ float g_sum[HH];
__device__ float g_sumsq[HH];
__device__ float g_ginv[HH];
__device__ float g_shift[HH];
__device__ float g_nsum[NN];             // per-node softmax denominator
__device__ unsigned char g_flag[EN];     // is-original-edge flag
__device__ float g_prec[NRELC * HH];

// ---------------- helpers ----------------
__device__ __forceinline__ uint32_t tf32u(float x) {
    uint32_t o; asm("cvt.rna.tf32.f32 %0, %1;" : "=r"(o) : "f"(x)); return o;
}
__device__ __forceinline__ void mma_tf32(float c[4], const uint32_t a[4],
                                         const uint32_t b[2]) {
    asm volatile(
        "mma.sync.aligned.m16n8k8.row.col.f32.tf32.tf32.f32 "
        "{%0,%1,%2,%3}, {%4,%5,%6,%7}, {%8,%9}, {%0,%1,%2,%3};"
        : "+f"(c[0]), "+f"(c[1]), "+f"(c[2]), "+f"(c[3])
        : "r"(a[0]), "r"(a[1]), "r"(a[2]), "r"(a[3]), "r"(b[0]), "r"(b[1]));
}
// pack k and k+4 adjacent: one LDS.64 per B fragment
__device__ __forceinline__ int permk(int k) {
    return (k & ~7) | ((k & 3) << 1) | ((k >> 2) & 1);
}

// ---------------- small kernels ----------------
__global__ void k_init() {
    int i = blockIdx.x * blockDim.x + threadIdx.x;
    if (i < HH) { g_sum[i] = 0.f; g_sumsq[i] = 0.f; }
    if (i < NN) g_nsum[i] = 0.f;
    if (i < EN) g_flag[i] = 0;
}
__global__ void k_flag(const int* __restrict__ ori) {
    int i = blockIdx.x * blockDim.x + threadIdx.x;
    if (i < EORI) g_flag[ori[i]] = 1;
}
__global__ void k_prec(const float* __restrict__ rel,
                       const float* __restrict__ W0,
                       const float* __restrict__ b0) {
    int i = blockIdx.x * blockDim.x + threadIdx.x;
    if (i >= NRELC * HH) return;
    int r = i / HH, c = i % HH;
    float s = b0[c];
#pragma unroll
    for (int k = 0; k < RR; k++)
        s = fmaf(rel[r * RR + k], W0[(DD + k) * HH + c], s);
    g_prec[i] = s;
}

// ---------------- pass1 ------------------------------------------------------
// Persistent 148 x 512 (16 warps). Tile = 128 edges x 128 ch, K = 128.
// Warp grid 4(m) x 4(n); warp tile 32x32 via m16n8k8 tf32.
// Phase order per iteration: sync, MMA(t), sync, produce(t+GRID), epilogue(t)
// -> produce LDG stalls overlap with other warps' epilogue STG work.

__device__ __forceinline__ void produce128(uint32_t* __restrict__ As,
                                           const float* __restrict__ nf,
                                           const int* __restrict__ rowv,
                                           const int* __restrict__ colv,
                                           int tile, int wid, int lane) {
    const int e0 = tile * 128 + wid * 8;
    int idx = 0;
    {
        int q = e0 + (lane & 7);
        q = (q < EN) ? q : (EN - 1);
        if (lane < 16) idx = (lane < 8) ? rowv[q] : colv[q];
    }
#pragma unroll 2
    for (int i = 0; i < 8; i++) {
        const int rn = __shfl_sync(0xffffffffu, idx, i);
        const int cn = __shfl_sync(0xffffffffu, idx, i + 8);
        float4 a = *(const float4*)(nf + (size_t)rn * DD + lane * 4);
        float4 b = *(const float4*)(nf + (size_t)cn * DD + lane * 4);
        uint4 s;
        s.x = tf32u(exp2f(-L2E * fabsf(a.x - b.x)));
        s.y = tf32u(exp2f(-L2E * fabsf(a.y - b.y)));
        s.z = tf32u(exp2f(-L2E * fabsf(a.z - b.z)));
        s.w = tf32u(exp2f(-L2E * fabsf(a.w - b.w)));
        *(uint4*)(As + (wid * 8 + i) * AS_STRIDE + lane * 4) = s;
    }
}

__global__ __launch_bounds__(512, 1) void k_pass1(
    const float* __restrict__ nf,
    const float* __restrict__ W0,
    const int* __restrict__ rowv,
    const int* __restrict__ colv,
    const int* __restrict__ etype) {
    extern __shared__ uint32_t sm[];
    uint32_t* Bs = sm + BS_OFF;              // [128 n][BS_STRIDE perm-k]
    uint32_t* As = sm + AS_OFF;              // [128 m][AS_STRIDE k]
    float* ssum = (float*)(sm + STAT_OFF);
    float* ssq  = ssum + 128;

    const int tid = threadIdx.x;
    const int wid = tid >> 5, lane = tid & 31;
    const int gid = lane >> 2, tg = lane & 3;
    const int wm = wid >> 2, wn = wid & 3;
    const int m0 = wm * 32, n0 = wn * 32;
    float2* stg = (float2*)(sm + STG_OFF) + wid * 32 * STG_STRIDE;

    // B = W0[:128,:] tf32 bits, [n][perm(k)]
    for (int i = tid; i < 128 * 128; i += 512) {
        int k = i >> 7, n = i & 127;
        Bs[n * BS_STRIDE + permk(k)] = tf32u(W0[i]);
    }
    if (tid < HH) { ssum[tid] = 0.f; ssq[tid] = 0.f; }

    // per-thread BN accumulators; col(nt,h) = n0 + nt*8 + tg*2 + h
    float ps[8], pq[8];
#pragma unroll
    for (int i = 0; i < 8; i++) { ps[i] = 0.f; pq[i] = 0.f; }

    // prologue: produce first tile
    produce128(As, nf, rowv, colv, blockIdx.x, wid, lane);

    for (int tile = blockIdx.x; tile < NT; tile += GRID1) {
        __syncthreads();   // As(t) visible; prior epilogues done

        // prefetch etype for this warp's 4 epilogue rows (hides under MMA)
        int et4[4];
#pragma unroll
        for (int q = 0; q < 4; q++) {
            const int row = m0 + (q >> 1) * 16 + (q & 1) * 8 + gid;
            const int e = tile * 128 + row;
            et4[q] = (e < EN) ? etype[e] : 0;
        }

        // ---- MMA: 2 m-tiles x 4 n-tiles x 16 k-tiles ----
        float acc[2][4][4];
#pragma unroll
        for (int mt = 0; mt < 2; mt++)
#pragma unroll
            for (int nt = 0; nt < 4; nt++)
#pragma unroll
                for (int r = 0; r < 4; r++) acc[mt][nt][r] = 0.f;

#pragma unroll
        for (int kt = 0; kt < 16; kt++) {
            const int k0 = kt * 8;
            uint32_t afr[2][4];
#pragma unroll
            for (int mt = 0; mt < 2; mt++) {
                const uint32_t* ab = As + (m0 + mt * 16 + gid) * AS_STRIDE + k0 + tg;
                afr[mt][0] = ab[0];
                afr[mt][1] = ab[8 * AS_STRIDE];
                afr[mt][2] = ab[4];
                afr[mt][3] = ab[8 * AS_STRIDE + 4];
            }
            uint32_t bfr[4][2];
#pragma unroll
            for (int nt = 0; nt < 4; nt++) {
                uint2 bb = *(const uint2*)(Bs + (n0 + nt * 8 + gid) * BS_STRIDE
                                           + k0 + tg * 2);
                bfr[nt][0] = bb.x;
                bfr[nt][1] = bb.y;
            }
#pragma unroll
            for (int mt = 0; mt < 2; mt++)
#pragma unroll
                for (int nt = 0; nt < 4; nt++)
                    mma_tf32(acc[mt][nt], afr[mt], bfr[nt]);
        }
        __syncthreads();   // all warps done reading As(t)

        // ---- produce NEXT tile into As (epilogue below doesn't touch As) ----
        if (tile + GRID1 < NT)
            produce128(As, nf, rowv, colv, tile + GRID1, wid, lane);

        // ---- epilogue: + prec, stats, stage in smem, coalesced STG.128 ----
#pragma unroll
        for (int mt = 0; mt < 2; mt++) {
#pragma unroll
            for (int rr = 0; rr < 2; rr++) {
                const int lrow = mt * 16 + rr * 8 + gid;
                const int e = tile * 128 + m0 + lrow;
                if (e < EN) {
                    const int et = et4[mt * 2 + rr];
                    const float2* prow = (const float2*)(g_prec + et * HH);
#pragma unroll
                    for (int nt = 0; nt < 4; nt++) {
                        const int c2g = (n0 + nt * 8 + tg * 2) >> 1;
                        float2 p = prow[c2g];
                        float v0 = acc[mt][nt][rr * 2 + 0] + p.x;
                        float v1 = acc[mt][nt][rr * 2 + 1] + p.y;
                        stg[lrow * STG_STRIDE + nt * 4 + tg] = make_float2(v0, v1);
                        ps[nt * 2 + 0] += v0; pq[nt * 2 + 0] = fmaf(v0, v0, pq[nt * 2 + 0]);
                        ps[nt * 2 + 1] += v1; pq[nt * 2 + 1] = fmaf(v1, v1, pq[nt * 2 + 1]);
                    }
                }
            }
        }
        __syncwarp();
#pragma unroll
        for (int s = 0; s < 8; s++) {
            const int lrow = s * 4 + (lane >> 3);
            const int e = tile * 128 + m0 + lrow;
            if (e < EN) {
                float4 v = *(const float4*)(stg + lrow * STG_STRIDE + (lane & 7) * 2);
                *(float4*)(g_h + (size_t)e * HH + n0 + (lane & 7) * 4) = v;
            }
        }
        __syncwarp();
    }

    // ---- final BN stat reduction: regs -> smem -> global ----
    __syncthreads();
#pragma unroll
    for (int nt = 0; nt < 4; nt++) {
#pragma unroll
        for (int h = 0; h < 2; h++) {
            const int col = n0 + nt * 8 + tg * 2 + h;
            atomicAdd(&ssum[col], ps[nt * 2 + h]);
            atomicAdd(&ssq[col], pq[nt * 2 + h]);
        }
    }
    __syncthreads();
    if (tid < HH) {
        atomicAdd(&g_sum[tid], ssum[tid]);
        atomicAdd(&g_sumsq[tid], ssq[tid]);
    }
}

// ---------------- BN params ----------------
__global__ void k_stats(const float* __restrict__ gamma,
                        const float* __restrict__ beta) {
    int c = threadIdx.x;
    if (c >= HH) return;
    float mu = g_sum[c] * (1.0f / EN);
    float var = g_sumsq[c] * (1.0f / EN) - mu * mu;
    float gi = gamma[c] * rsqrtf(var + 1e-5f);
    g_ginv[c] = gi;
    g_shift[c] = beta[c] - mu * gi;
}

// ---------------- pass3: w = leaky(BN(h))@W1 + b1, blend, exp, node sum -------
// Softmax is shift-invariant; BN-bounded logits make exp(w) safe in f32,
// so the segment-max pass is eliminated.
__global__ __launch_bounds__(256) void k_pass3(const int* __restrict__ colv,
                                               const float* __restrict__ W1,
                                               const float* __restrict__ b1) {
    int lane = threadIdx.x & 31;
    int warp = (blockIdx.x * blockDim.x + threadIdx.x) >> 5;
    int nwarp = (gridDim.x * blockDim.x) >> 5;
    float4 gi = *(const float4*)(g_ginv + lane * 4);
    float4 sh = *(const float4*)(g_shift + lane * 4);
    float4 w1 = *(const float4*)(W1 + lane * 4);
    float b1v = b1[0];
    for (int e = warp; e < EN; e += nwarp) {
        float4 h = *(const float4*)(g_h + (size_t)e * HH + lane * 4);
        float t, l, s;
        t = fmaf(h.x, gi.x, sh.x); l = fmaxf(t, 0.f) + 0.01f * fminf(t, 0.f); s = l * w1.x;
        t = fmaf(h.y, gi.y, sh.y); l = fmaxf(t, 0.f) + 0.01f * fminf(t, 0.f); s = fmaf(l, w1.y, s);
        t = fmaf(h.z, gi.z, sh.z); l = fmaxf(t, 0.f) + 0.01f * fminf(t, 0.f); s = fmaf(l, w1.z, s);
        t = fmaf(h.w, gi.w, sh.w); l = fmaxf(t, 0.f) + 0.01f * fminf(t, 0.f); s = fmaf(l, w1.w, s);
        s += __shfl_xor_sync(0xffffffffu, s, 16);
        s += __shfl_xor_sync(0xffffffffu, s, 8);
        s += __shfl_xor_sync(0xffffffffu, s, 4);
        s += __shfl_xor_sync(0xffffffffu, s, 2);
        s += __shfl_xor_sync(0xffffffffu, s, 1);
        if (lane == 0) {
            float wv = s + b1v;
            if (g_flag[e]) wv = 0.5f * wv + 0.5f;
            float ev = exp2f(wv * L2E);
            g_w[e] = ev;
            atomicAdd(&g_nsum[colv[e]], ev);
        }
    }
}

__global__ void k_pass5(const int* __restrict__ colv, float* __restrict__ out) {
    int e = blockIdx.x * blockDim.x + threadIdx.x;
    if (e >= EN) return;
    int cn = colv[e];
    float o = g_w[e] / g_nsum[cn];
    out[e] = (o > 1e-4f) ? o : 0.f;
}

// ---------------- launch ----------------
extern "C" void kernel_launch(void* const* d_in, const int* in_sizes, int n_in,
                              void* d_out, int out_size) {
    const float* n_feat  = (const float*)d_in[0];
    const float* rel_emb = (const float*)d_in[1];
    const float* W0      = (const float*)d_in[2];
    const float* b0      = (const float*)d_in[3];
    const float* gamma   = (const float*)d_in[4];
    const float* beta    = (const float*)d_in[5];
    const float* W1      = (const float*)d_in[6];
    const float* b1      = (const float*)d_in[7];
    const int*   rowv    = (const int*)d_in[8];
    const int*   colv    = (const int*)d_in[9];
    const int*   etype   = (const int*)d_in[10];
    const int*   ori     = (const int*)d_in[11];
    float* out = (float*)d_out;

    const int smem1 = SMEM_U32 * 4;   // 220,160 B
    static bool attr_done = false;
    if (!attr_done) {
        cudaFuncSetAttribute(k_pass1, cudaFuncAttributeMaxDynamicSharedMemorySize, smem1);
        attr_done = true;
    }

    k_init<<<(EN + 255) / 256, 256>>>();
    k_flag<<<(EORI + 255) / 256, 256>>>(ori);
    k_prec<<<(NRELC * HH + 255) / 256, 256>>>(rel_emb, W0, b0);
    k_pass1<<<GRID1, 512, smem1>>>(n_feat, W0, rowv, colv, etype);
    k_stats<<<1, 128>>>(gamma, beta);
    k_pass3<<<2048, 256>>>(colv, W1, b1);
    k_pass5<<<(EN + 255) / 256, 256>>>(colv, out);
}

// round 11
// speedup vs baseline: 1.6160x; 1.0291x over previous
#include <cuda_runtime.h>
#include <cstdint>
#include <cstddef>

// Problem constants
#define EN    1000000
#define NN    100000
#define EORI  200000
#define DD    128
#define RR    32
#define HH    128
#define NRELC 200
#define L2E   1.4426950408889634f

#define NT    7813          // ceil(EN/128)
#define GRID1 148

#define AS_STRIDE 132       // floats; conflict-free A-fragment LDS
#define BS_STRIDE 136       // floats; [n][perm(k)] rows

// smem offsets (uint32 units)
#define BS_OFF   0
#define AS_OFF   (128 * BS_STRIDE)                    // 17408
#define ABUF_U32 (128 * AS_STRIDE)                    // 16896
#define STAT_OFF (AS_OFF + 2 * ABUF_U32)              // 51200
#define STG_OFF  (STAT_OFF + 256)                     // 51456
#define SMEM_U32 (STG_OFF + 16 * 320)                 // 56576 -> 226304 B

// ---------------- scratch globals ----------------
__device__ float g_h[(size_t)EN * HH];   // 512 MB pre-BN activations
__device__ float g_w[EN];                // exp(w) per edge
__device__ float g_sum[HH];
__device__ float g_sumsq[HH];
__device__ float g_ginv[HH];
__device__ float g_shift[HH];
__device__ float g_nsum[NN];             // per-node softmax denominator
__device__ unsigned char g_flag[EN];     // is-original-edge flag
__device__ float g_prec[NRELC * HH];

// ---------------- helpers ----------------
__device__ __forceinline__ uint32_t tf32u(float x) {
    uint32_t o; asm("cvt.rna.tf32.f32 %0, %1;" : "=r"(o) : "f"(x)); return o;
}
__device__ __forceinline__ void mma_tf32(float c[4], const uint32_t a[4],
                                         const uint32_t b[2]) {
    asm volatile(
        "mma.sync.aligned.m16n8k8.row.col.f32.tf32.tf32.f32 "
        "{%0,%1,%2,%3}, {%4,%5,%6,%7}, {%8,%9}, {%0,%1,%2,%3};"
        : "+f"(c[0]), "+f"(c[1]), "+f"(c[2]), "+f"(c[3])
        : "r"(a[0]), "r"(a[1]), "r"(a[2]), "r"(a[3]), "r"(b[0]), "r"(b[1]));
}
// pack k and k+4 adjacent: one LDS.64 per B fragment
__device__ __forceinline__ int permk(int k) {
    return (k & ~7) | ((k & 3) << 1) | ((k >> 2) & 1);
}

// ---------------- setup kernels ----------------
__global__ void k_setup(const float* __restrict__ rel,
                        const float* __restrict__ W0,
                        const float* __restrict__ b0) {
    int i = blockIdx.x * blockDim.x + threadIdx.x;
    if (i < HH) { g_sum[i] = 0.f; g_sumsq[i] = 0.f; }
    if (i < NN) g_nsum[i] = 0.f;
    if (i < EN) g_flag[i] = 0;
    if (i < NRELC * HH) {
        int r = i / HH, c = i % HH;
        float s = b0[c];
#pragma unroll
        for (int k = 0; k < RR; k++)
            s = fmaf(rel[r * RR + k], W0[(DD + k) * HH + c], s);
        g_prec[i] = s;
    }
}
__global__ void k_flag(const int* __restrict__ ori) {
    int i = blockIdx.x * blockDim.x + threadIdx.x;
    if (i < EORI) g_flag[ori[i]] = 1;
}

// ---------------- pass1 ------------------------------------------------------
// Persistent 148 x 512 (16 warps). Tile = 128 edges x 128 ch, K = 128.
// Warp grid 4(m) x 4(n); warp tile 32x32 via m16n8k8 tf32.
// Double-buffered As, ONE barrier per tile:
//   sync -> MMA(Ab) -> produce(t+GRID -> An) -> chunked staged epilogue.

__device__ __forceinline__ void produce128(uint32_t* __restrict__ As,
                                           const float* __restrict__ nf,
                                           const int* __restrict__ rowv,
                                           const int* __restrict__ colv,
                                           int tile, int wid, int lane) {
    const int e0 = tile * 128 + wid * 8;
    int idx = 0;
    {
        int q = e0 + (lane & 7);
        q = (q < EN) ? q : (EN - 1);
        if (lane < 16) idx = (lane < 8) ? rowv[q] : colv[q];
    }
#pragma unroll 2
    for (int i = 0; i < 8; i++) {
        const int rn = __shfl_sync(0xffffffffu, idx, i);
        const int cn = __shfl_sync(0xffffffffu, idx, i + 8);
        float4 a = *(const float4*)(nf + (size_t)rn * DD + lane * 4);
        float4 b = *(const float4*)(nf + (size_t)cn * DD + lane * 4);
        uint4 s;
        s.x = tf32u(exp2f(-L2E * fabsf(a.x - b.x)));
        s.y = tf32u(exp2f(-L2E * fabsf(a.y - b.y)));
        s.z = tf32u(exp2f(-L2E * fabsf(a.z - b.z)));
        s.w = tf32u(exp2f(-L2E * fabsf(a.w - b.w)));
        *(uint4*)(As + (wid * 8 + i) * AS_STRIDE + lane * 4) = s;
    }
}

__global__ __launch_bounds__(512, 1) void k_pass1(
    const float* __restrict__ nf,
    const float* __restrict__ W0,
    const int* __restrict__ rowv,
    const int* __restrict__ colv,
    const int* __restrict__ etype) {
    extern __shared__ uint32_t sm[];
    uint32_t* Bs = sm + BS_OFF;              // [128 n][BS_STRIDE perm-k]
    uint32_t* As0 = sm + AS_OFF;             // [128 m][AS_STRIDE k] x2
    uint32_t* As1 = As0 + ABUF_U32;
    float* ssum = (float*)(sm + STAT_OFF);
    float* ssq  = ssum + 128;

    const int tid = threadIdx.x;
    const int wid = tid >> 5, lane = tid & 31;
    const int gid = lane >> 2, tg = lane & 3;
    const int wm = wid >> 2, wn = wid & 3;
    const int m0 = wm * 32, n0 = wn * 32;
    float2* stg = (float2*)(sm + STG_OFF) + wid * 160;  // 8 rows x 20 float2

    // B = W0[:128,:] tf32 bits, [n][perm(k)]
    for (int i = tid; i < 128 * 128; i += 512) {
        int k = i >> 7, n = i & 127;
        Bs[n * BS_STRIDE + permk(k)] = tf32u(W0[i]);
    }
    if (tid < HH) { ssum[tid] = 0.f; ssq[tid] = 0.f; }

    // per-thread BN accumulators; col(nt,h) = n0 + nt*8 + tg*2 + h
    float ps[8], pq[8];
#pragma unroll
    for (int i = 0; i < 8; i++) { ps[i] = 0.f; pq[i] = 0.f; }

    // prologue: produce first tile into As0
    produce128(As0, nf, rowv, colv, blockIdx.x, wid, lane);

    int it = 0;
    for (int tile = blockIdx.x; tile < NT; tile += GRID1, it++) {
        uint32_t* Ab = (it & 1) ? As1 : As0;
        uint32_t* An = (it & 1) ? As0 : As1;
        __syncthreads();   // Ab fully produced; prior iter fully done

        // prefetch etype for this warp's 4 epilogue chunks (hides under MMA)
        int et4[4];
#pragma unroll
        for (int q = 0; q < 4; q++) {
            const int row = m0 + (q >> 1) * 16 + (q & 1) * 8 + gid;
            const int e = tile * 128 + row;
            et4[q] = (e < EN) ? etype[e] : 0;
        }

        // ---- MMA: 2 m-tiles x 4 n-tiles x 16 k-tiles ----
        float acc[2][4][4];
#pragma unroll
        for (int mt = 0; mt < 2; mt++)
#pragma unroll
            for (int nt = 0; nt < 4; nt++)
#pragma unroll
                for (int r = 0; r < 4; r++) acc[mt][nt][r] = 0.f;

#pragma unroll
        for (int kt = 0; kt < 16; kt++) {
            const int k0 = kt * 8;
            uint32_t afr[2][4];
#pragma unroll
            for (int mt = 0; mt < 2; mt++) {
                const uint32_t* ab = Ab + (m0 + mt * 16 + gid) * AS_STRIDE + k0 + tg;
                afr[mt][0] = ab[0];
                afr[mt][1] = ab[8 * AS_STRIDE];
                afr[mt][2] = ab[4];
                afr[mt][3] = ab[8 * AS_STRIDE + 4];
            }
            uint32_t bfr[4][2];
#pragma unroll
            for (int nt = 0; nt < 4; nt++) {
                uint2 bb = *(const uint2*)(Bs + (n0 + nt * 8 + gid) * BS_STRIDE
                                           + k0 + tg * 2);
                bfr[nt][0] = bb.x;
                bfr[nt][1] = bb.y;
            }
#pragma unroll
            for (int mt = 0; mt < 2; mt++)
#pragma unroll
                for (int nt = 0; nt < 4; nt++)
                    mma_tf32(acc[mt][nt], afr[mt], bfr[nt]);
        }

        // ---- produce NEXT tile into the other buffer (no barrier needed) ----
        if (tile + GRID1 < NT)
            produce128(An, nf, rowv, colv, tile + GRID1, wid, lane);

        // ---- epilogue: 4 chunks of 8 rows, staged, coalesced STG.128 ----
#pragma unroll
        for (int mt = 0; mt < 2; mt++) {
#pragma unroll
            for (int rr = 0; rr < 2; rr++) {
                const int rbase = tile * 128 + m0 + mt * 16 + rr * 8;
                const bool valid = (rbase + gid) < EN;  // uniform per chunk
                if (valid) {
                    const int et = et4[mt * 2 + rr];
                    const float2* prow = (const float2*)(g_prec + et * HH);
#pragma unroll
                    for (int nt = 0; nt < 4; nt++) {
                        const int c2g = (n0 + nt * 8 + tg * 2) >> 1;
                        float2 p = prow[c2g];
                        float v0 = acc[mt][nt][rr * 2 + 0] + p.x;
                        float v1 = acc[mt][nt][rr * 2 + 1] + p.y;
                        stg[gid * 20 + nt * 4 + tg] = make_float2(v0, v1);
                        ps[nt * 2 + 0] += v0; pq[nt * 2 + 0] = fmaf(v0, v0, pq[nt * 2 + 0]);
                        ps[nt * 2 + 1] += v1; pq[nt * 2 + 1] = fmaf(v1, v1, pq[nt * 2 + 1]);
                    }
                }
                __syncwarp();
#pragma unroll
                for (int s = 0; s < 2; s++) {
                    const int r = (lane >> 3) + s * 4;     // local row 0..7
                    const int c = lane & 7;                // float4 index
                    const int e = rbase + r;
                    if (e < EN) {
                        float4 v = *(const float4*)((const float*)stg + r * 40 + c * 4);
                        __stcs((float4*)(g_h + (size_t)e * HH + n0 + c * 4), v);
                    }
                }
                __syncwarp();
            }
        }
    }

    // ---- final BN stat reduction: regs -> smem -> global ----
    __syncthreads();
#pragma unroll
    for (int nt = 0; nt < 4; nt++) {
#pragma unroll
        for (int h = 0; h < 2; h++) {
            const int col = n0 + nt * 8 + tg * 2 + h;
            atomicAdd(&ssum[col], ps[nt * 2 + h]);
            atomicAdd(&ssq[col], pq[nt * 2 + h]);
        }
    }
    __syncthreads();
    if (tid < HH) {
        atomicAdd(&g_sum[tid], ssum[tid]);
        atomicAdd(&g_sumsq[tid], ssq[tid]);
    }
}

// ---------------- BN params ----------------
__global__ void k_stats(const float* __restrict__ gamma,
                        const float* __restrict__ beta) {
    int c = threadIdx.x;
    if (c >= HH) return;
    float mu = g_sum[c] * (1.0f / EN);
    float var = g_sumsq[c] * (1.0f / EN) - mu * mu;
    float gi = gamma[c] * rsqrtf(var + 1e-5f);
    g_ginv[c] = gi;
    g_shift[c] = beta[c] - mu * gi;
}

// ---------------- pass3: w = leaky(BN(h))@W1 + b1, blend, exp, node sum -------
__global__ __launch_bounds__(256) void k_pass3(const int* __restrict__ colv,
                                               const float* __restrict__ W1,
                                               const float* __restrict__ b1) {
    int lane = threadIdx.x & 31;
    int warp = (blockIdx.x * blockDim.x + threadIdx.x) >> 5;
    int nwarp = (gridDim.x * blockDim.x) >> 5;
    float4 gi = *(const float4*)(g_ginv + lane * 4);
    float4 sh = *(const float4*)(g_shift + lane * 4);
    float4 w1 = *(const float4*)(W1 + lane * 4);
    float b1v = b1[0];
    for (int e = warp; e < EN; e += nwarp) {
        float4 h = __ldcs((const float4*)(g_h + (size_t)e * HH + lane * 4));
        float t, l, s;
        t = fmaf(h.x, gi.x, sh.x); l = fmaxf(t, 0.f) + 0.01f * fminf(t, 0.f); s = l * w1.x;
        t = fmaf(h.y, gi.y, sh.y); l = fmaxf(t, 0.f) + 0.01f * fminf(t, 0.f); s = fmaf(l, w1.y, s);
        t = fmaf(h.z, gi.z, sh.z); l = fmaxf(t, 0.f) + 0.01f * fminf(t, 0.f); s = fmaf(l, w1.z, s);
        t = fmaf(h.w, gi.w, sh.w); l = fmaxf(t, 0.f) + 0.01f * fminf(t, 0.f); s = fmaf(l, w1.w, s);
        s += __shfl_xor_sync(0xffffffffu, s, 16);
        s += __shfl_xor_sync(0xffffffffu, s, 8);
        s += __shfl_xor_sync(0xffffffffu, s, 4);
        s += __shfl_xor_sync(0xffffffffu, s, 2);
        s += __shfl_xor_sync(0xffffffffu, s, 1);
        if (lane == 0) {
            float wv = s + b1v;
            if (g_flag[e]) wv = 0.5f * wv + 0.5f;
            float ev = exp2f(wv * L2E);
            g_w[e] = ev;
            atomicAdd(&g_nsum[colv[e]], ev);
        }
    }
}

__global__ void k_pass5(const int* __restrict__ colv, float* __restrict__ out) {
    int e = blockIdx.x * blockDim.x + threadIdx.x;
    if (e >= EN) return;
    int cn = colv[e];
    float o = __ldcs(&g_w[e]) / g_nsum[cn];
    out[e] = (o > 1e-4f) ? o : 0.f;
}

// ---------------- launch ----------------
extern "C" void kernel_launch(void* const* d_in, const int* in_sizes, int n_in,
                              void* d_out, int out_size) {
    const float* n_feat  = (const float*)d_in[0];
    const float* rel_emb = (const float*)d_in[1];
    const float* W0      = (const float*)d_in[2];
    const float* b0      = (const float*)d_in[3];
    const float* gamma   = (const float*)d_in[4];
    const float* beta    = (const float*)d_in[5];
    const float* W1      = (const float*)d_in[6];
    const float* b1      = (const float*)d_in[7];
    const int*   rowv    = (const int*)d_in[8];
    const int*   colv    = (const int*)d_in[9];
    const int*   etype   = (const int*)d_in[10];
    const int*   ori     = (const int*)d_in[11];
    float* out = (float*)d_out;

    const int smem1 = SMEM_U32 * 4;   // 226,304 B
    static bool attr_done = false;
    if (!attr_done) {
        cudaFuncSetAttribute(k_pass1, cudaFuncAttributeMaxDynamicSharedMemorySize, smem1);
        attr_done = true;
    }

    k_setup<<<(EN + 255) / 256, 256>>>(rel_emb, W0, b0);
    k_flag<<<(EORI + 255) / 256, 256>>>(ori);
    k_pass1<<<GRID1, 512, smem1>>>(n_feat, W0, rowv, colv, etype);
    k_stats<<<1, 128>>>(gamma, beta);
    k_pass3<<<2048, 256>>>(colv, W1, b1);
    k_pass5<<<(EN + 255) / 256, 256>>>(colv, out);
}